// round 10
// baseline (speedup 1.0000x reference)
#include <cuda_runtime.h>
#include <cuda_bf16.h>
#include <cstdint>
#include <cstdio>

// ---------------------------------------------------------------------------
// Problem constants
// ---------------------------------------------------------------------------
#define NMAX 200192        // >= N (=200000) and >= M
#define NBLK_STATS 240
#define BN_EPS 1e-4

// ---------------------------------------------------------------------------
// Static device scratch
// ---------------------------------------------------------------------------
__device__ __nv_bfloat16 g_t0b[(NMAX + 1) * 64];    // bn1 split [hi32|lo32]
__device__ float         g_x1[NMAX * 32];           // sub1 out (skip)
__device__ __nv_bfloat16 g_t1b[(NMAX + 1) * 64];    // bn2 split
__device__ float         g_xc0[NMAX * 64];          // down out
__device__ __nv_bfloat16 g_t2b[(NMAX + 1) * 128];   // bn3 split [hi64|lo64]
__device__ float         g_xc1[NMAX * 64];          // sub2 out
__device__ float         g_t3[(NMAX + 1) * 64];     // bn4 fp32 (deconv input)
__device__ float         g_xf[NMAX * 32];           // deconv out
__device__ __nv_bfloat16 g_t4b[(NMAX + 1) * 128];   // bn5(concat) split
__device__ double        g_part[NBLK_STATS * 128];
__device__ float         g_scale[5 * 64];
__device__ float         g_shift[5 * 64];

// Pre-baked B fragment blobs: per tap, [2*NK ksteps (hi then lo)][NT][32 lanes][uint2]
__device__ __align__(16) uint8_t g_wb1[27 * 4096];    // sub1  (32->32)
__device__ __align__(16) uint8_t g_wbD[8 * 8192];     // down  (32->64)
__device__ __align__(16) uint8_t g_wb2[27 * 16384];   // sub2  (64->64)
__device__ __align__(16) uint8_t g_wb3[27 * 8192];    // sub3  (64->32)

// Rulebooks: two sets (F = fine, C = coarse/down), 27 regions of NMAX pairs
__device__ int g_cntF[28], g_goffF[28], g_totF[1];
__device__ int g_pmF[27 * NMAX], g_piF[27 * NMAX];
__device__ int g_cntC[28], g_goffC[28], g_totC[1];
__device__ int g_pmC[27 * NMAX], g_piC[27 * NMAX];

// ---------------------------------------------------------------------------
// MMA helpers (sm_80-era PTX; compiles for plain compute_103)
// ---------------------------------------------------------------------------
__device__ __forceinline__ uint32_t smem_u32(const void* p) {
    return (uint32_t)__cvta_generic_to_shared(p);
}
__device__ __forceinline__ void ldm_x4(uint32_t r[4], uint32_t addr) {
    asm volatile("ldmatrix.sync.aligned.m8n8.x4.shared.b16 {%0,%1,%2,%3}, [%4];"
                 : "=r"(r[0]), "=r"(r[1]), "=r"(r[2]), "=r"(r[3]) : "r"(addr));
}
__device__ __forceinline__ void mma16816(float* d, const uint32_t* a, uint2 b) {
    asm volatile(
        "mma.sync.aligned.m16n8k16.row.col.f32.bf16.bf16.f32 "
        "{%0,%1,%2,%3}, {%4,%5,%6,%7}, {%8,%9}, {%0,%1,%2,%3};"
        : "+f"(d[0]), "+f"(d[1]), "+f"(d[2]), "+f"(d[3])
        : "r"(a[0]), "r"(a[1]), "r"(a[2]), "r"(a[3]), "r"(b.x), "r"(b.y));
}
__device__ __forceinline__ void sts128(uint32_t addr, uint4 v) {
    asm volatile("st.shared.v4.b32 [%0], {%1,%2,%3,%4};"
                 :: "r"(addr), "r"(v.x), "r"(v.y), "r"(v.z), "r"(v.w));
}

// ---------------------------------------------------------------------------
// BN stats pass 1: deterministic per-block partial sums (double)
// ---------------------------------------------------------------------------
template <int C>
__global__ __launch_bounds__(256) void bn_stats1(const float* __restrict__ x,
                                                 int rows,
                                                 double* __restrict__ partial) {
    __shared__ double ss[256], sq[256];
    int tid = threadIdx.x;
    long long total = (long long)rows * C;
    double s = 0.0, q = 0.0;
    for (long long i = (long long)blockIdx.x * 256 + tid; i < total;
         i += (long long)gridDim.x * 256) {
        double v = (double)x[i];
        s += v;
        q += v * v;
    }
    ss[tid] = s;
    sq[tid] = q;
    for (int st = 128; st >= C; st >>= 1) {
        __syncthreads();
        if (tid < st) { ss[tid] += ss[tid + st]; sq[tid] += sq[tid + st]; }
    }
    if (tid < C) {
        partial[blockIdx.x * 128 + tid]      = ss[tid];
        partial[blockIdx.x * 128 + 64 + tid] = sq[tid];
    }
}

__global__ void bn_stats2(const double* __restrict__ partial, int nblk, int rows,
                          const float* __restrict__ g, const float* __restrict__ b,
                          float* __restrict__ sc, float* __restrict__ sh, int C) {
    int c = threadIdx.x;
    if (c >= C) return;
    double s = 0.0, q = 0.0;
    for (int i = 0; i < nblk; i++) {
        s += partial[i * 128 + c];
        q += partial[i * 128 + 64 + c];
    }
    double mean = s / rows;
    double var  = q / rows - mean * mean;
    double inv  = 1.0 / sqrt(var + BN_EPS);
    double scale = (double)g[c] * inv;
    sc[c] = (float)scale;
    sh[c] = (float)((double)b[c] - mean * scale);
}

// ---------------------------------------------------------------------------
// BN apply + ReLU + bf16 hi/lo split helpers
// ---------------------------------------------------------------------------
__device__ __forceinline__ void split4(float4 d, uint2& hi, uint2& lo) {
    __nv_bfloat16 h0 = __float2bfloat16(d.x), h1 = __float2bfloat16(d.y);
    __nv_bfloat16 h2 = __float2bfloat16(d.z), h3 = __float2bfloat16(d.w);
    __nv_bfloat16 l0 = __float2bfloat16(d.x - __bfloat162float(h0));
    __nv_bfloat16 l1 = __float2bfloat16(d.y - __bfloat162float(h1));
    __nv_bfloat16 l2 = __float2bfloat16(d.z - __bfloat162float(h2));
    __nv_bfloat16 l3 = __float2bfloat16(d.w - __bfloat162float(h3));
    hi.x = ((uint32_t)__bfloat16_as_ushort(h1) << 16) | __bfloat16_as_ushort(h0);
    hi.y = ((uint32_t)__bfloat16_as_ushort(h3) << 16) | __bfloat16_as_ushort(h2);
    lo.x = ((uint32_t)__bfloat16_as_ushort(l1) << 16) | __bfloat16_as_ushort(l0);
    lo.y = ((uint32_t)__bfloat16_as_ushort(l3) << 16) | __bfloat16_as_ushort(l2);
}

template <int C>
__global__ __launch_bounds__(256) void bn_apply_split(const float* __restrict__ x,
                                                      __nv_bfloat16* __restrict__ y,
                                                      const float* __restrict__ sc,
                                                      const float* __restrict__ sh,
                                                      int rows) {
    int i = blockIdx.x * blockDim.x + threadIdx.x;
    if (i < C / 4) {
        uint2 z = make_uint2(0, 0);
        *reinterpret_cast<uint2*>(&y[(size_t)rows * 2 * C + 4 * i]) = z;
        *reinterpret_cast<uint2*>(&y[(size_t)rows * 2 * C + C + 4 * i]) = z;
    }
    int n4 = rows * C / 4;
    if (i < n4) {
        float4 d = reinterpret_cast<const float4*>(x)[i];
        int row = i / (C / 4);
        int c0 = (i % (C / 4)) * 4;
        d.x = fmaxf(fmaf(d.x, __ldg(&sc[c0 + 0]), __ldg(&sh[c0 + 0])), 0.f);
        d.y = fmaxf(fmaf(d.y, __ldg(&sc[c0 + 1]), __ldg(&sh[c0 + 1])), 0.f);
        d.z = fmaxf(fmaf(d.z, __ldg(&sc[c0 + 2]), __ldg(&sh[c0 + 2])), 0.f);
        d.w = fmaxf(fmaf(d.w, __ldg(&sc[c0 + 3]), __ldg(&sh[c0 + 3])), 0.f);
        uint2 hi, lo;
        split4(d, hi, lo);
        *reinterpret_cast<uint2*>(&y[(size_t)row * 2 * C + c0]) = hi;
        *reinterpret_cast<uint2*>(&y[(size_t)row * 2 * C + C + c0]) = lo;
    }
}

template <int C>
__global__ __launch_bounds__(256) void bn_apply(const float* __restrict__ x,
                                                float* __restrict__ y,
                                                const float* __restrict__ sc,
                                                const float* __restrict__ sh,
                                                int rows) {
    int i = blockIdx.x * blockDim.x + threadIdx.x;
    if (i < C / 4) {
        *reinterpret_cast<float4*>(&y[(size_t)rows * C + 4 * i]) =
            make_float4(0.f, 0.f, 0.f, 0.f);
    }
    int n4 = rows * C / 4;
    if (i < n4) {
        float4 d = reinterpret_cast<const float4*>(x)[i];
        int c0 = (i * 4) % C;
        d.x = fmaxf(fmaf(d.x, __ldg(&sc[c0 + 0]), __ldg(&sh[c0 + 0])), 0.f);
        d.y = fmaxf(fmaf(d.y, __ldg(&sc[c0 + 1]), __ldg(&sh[c0 + 1])), 0.f);
        d.z = fmaxf(fmaf(d.z, __ldg(&sc[c0 + 2]), __ldg(&sh[c0 + 2])), 0.f);
        d.w = fmaxf(fmaf(d.w, __ldg(&sc[c0 + 3]), __ldg(&sh[c0 + 3])), 0.f);
        reinterpret_cast<float4*>(y)[i] = d;
    }
}

__global__ __launch_bounds__(256) void bn_apply_cat_split(const float* __restrict__ x1,
                                                          const float* __restrict__ xf,
                                                          __nv_bfloat16* __restrict__ y,
                                                          const float* __restrict__ sc,
                                                          const float* __restrict__ sh,
                                                          int rows) {
    int i = blockIdx.x * blockDim.x + threadIdx.x;
    if (i < 16) {
        uint2 z = make_uint2(0, 0);
        *reinterpret_cast<uint2*>(&y[(size_t)rows * 128 + 4 * i]) = z;
        *reinterpret_cast<uint2*>(&y[(size_t)rows * 128 + 64 + 4 * i]) = z;
    }
    int n4 = rows * 16;
    if (i < n4) {
        int row = i / 16, q = i % 16;
        float4 d = (q < 8) ? reinterpret_cast<const float4*>(x1)[row * 8 + q]
                           : reinterpret_cast<const float4*>(xf)[row * 8 + (q - 8)];
        int c0 = q * 4;
        d.x = fmaxf(fmaf(d.x, __ldg(&sc[c0 + 0]), __ldg(&sh[c0 + 0])), 0.f);
        d.y = fmaxf(fmaf(d.y, __ldg(&sc[c0 + 1]), __ldg(&sh[c0 + 1])), 0.f);
        d.z = fmaxf(fmaf(d.z, __ldg(&sc[c0 + 2]), __ldg(&sh[c0 + 2])), 0.f);
        d.w = fmaxf(fmaf(d.w, __ldg(&sc[c0 + 3]), __ldg(&sh[c0 + 3])), 0.f);
        uint2 hi, lo;
        split4(d, hi, lo);
        *reinterpret_cast<uint2*>(&y[(size_t)row * 128 + c0]) = hi;
        *reinterpret_cast<uint2*>(&y[(size_t)row * 128 + 64 + c0]) = lo;
    }
}

// ---------------------------------------------------------------------------
// W prep: bake B fragments for mma.sync m16n8k16 (col-major B = W^T view).
// ---------------------------------------------------------------------------
template <int CIN, int COUT, int K>
__global__ void wprep(const float* __restrict__ W, uint8_t* __restrict__ blob) {
    constexpr int NK = CIN / 16;
    constexpr int NT = COUT / 8;
    constexpr int BBYTES = 2 * NK * NT * 32 * 8;
    int i = blockIdx.x * blockDim.x + threadIdx.x;
    if (i >= K * CIN * COUT) return;
    int k = i / (CIN * COUT);
    int r = i % (CIN * COUT);
    int ci = r / COUT, co = r % COUT;
    float w = W[i];
    __nv_bfloat16 hi = __float2bfloat16(w);
    __nv_bfloat16 lo = __float2bfloat16(w - __bfloat162float(hi));

    int ksg  = ci >> 4;
    int kloc = ci & 15;
    int reg  = kloc >> 3;
    int kl   = kloc & 7;
    int t    = kl >> 1;
    int half = kl & 1;
    int nt   = co >> 3;
    int gid  = co & 7;
    int lane = gid * 4 + t;

    uint8_t* base = blob + (size_t)k * BBYTES;
    size_t off_hi = ((size_t)(ksg * NT + nt) * 32 + lane) * 8 + reg * 4 + half * 2;
    size_t off_lo = ((size_t)((NK + ksg) * NT + nt) * 32 + lane) * 8 + reg * 4 + half * 2;
    *reinterpret_cast<__nv_bfloat16*>(base + off_hi) = hi;
    *reinterpret_cast<__nv_bfloat16*>(base + off_lo) = lo;
}

// ---------------------------------------------------------------------------
// Rulebook build: per-tap compacted (out_row, in_idx) pair lists
// ---------------------------------------------------------------------------
__global__ void pair_reset(int* cnt) {
    if (threadIdx.x < 28) cnt[threadIdx.x] = 0;
}

__global__ __launch_bounds__(256) void pair_build(const int* __restrict__ nbr,
                                                  int rows, int P, int ntaps,
                                                  int skiptap, int* cnt,
                                                  int* pm, int* pi) {
    int m = blockIdx.x * 256 + threadIdx.x;
    if (m >= rows) return;
    for (int k = 0; k < ntaps; k++) {
        if (k == skiptap) continue;
        int idx = __ldg(&nbr[(size_t)k * rows + m]);
        if (idx != P) {
            int s = atomicAdd(&cnt[k], 1);
            pm[k * NMAX + s] = m;
            pi[k * NMAX + s] = idx;
        }
    }
}

__global__ void pair_scan(const int* __restrict__ cnt, int* __restrict__ goff,
                          int* __restrict__ totg, int ntaps) {
    int k = threadIdx.x;  // 32 threads
    int c = (k < ntaps) ? (cnt[k] + 15) >> 4 : 0;
    int x = c;
    for (int o = 1; o < 32; o <<= 1) {
        int y = __shfl_up_sync(0xFFFFFFFFu, x, o);
        if (k >= o) x += y;
    }
    if (k < ntaps) goff[k] = x - c;
    if (k == ntaps - 1) { goff[ntaps] = x; totg[0] = x; }
}

__global__ __launch_bounds__(256) void zero_f(float* p, int n4) {
    int i = blockIdx.x * 256 + threadIdx.x;
    if (i < n4) reinterpret_cast<float4*>(p)[i] = make_float4(0.f, 0.f, 0.f, 0.f);
}

// ---------------------------------------------------------------------------
// Dense center-tap GEMM (tap 13 is identity: A row m = fb[m], no gather).
// 256 rows/CTA, 8 warps x 32 rows, bf16-split 3-term MMA, plain stores.
// ---------------------------------------------------------------------------
template <int CIN, int COUT>
__global__ __launch_bounds__(256, 2)
void gemm_center(const __nv_bfloat16* __restrict__ fb,
                 const uint8_t* __restrict__ blobtap,   // tap-13 fragments
                 float* __restrict__ out, int rows, int P) {
    constexpr int NK = CIN / 16;
    constexpr int NT = COUT / 8;
    constexpr int PITCH = 2 * CIN + 8;
    constexpr int ACH = CIN / 4;

    extern __shared__ __align__(16) uint8_t smem[];
    uint32_t a_u32 = smem_u32(smem);

    int tid = threadIdx.x;
    int w = tid >> 5, lane = tid & 31;
    int row0 = blockIdx.x * 256;
    int ggr = row0 + tid;
    int idx = (ggr < rows) ? ggr : P;

    uint32_t my_sts = a_u32 + (uint32_t)tid * (PITCH * 2);
    uint32_t ldm_base = a_u32 + (uint32_t)((w * 32 + (lane & 15)) * (PITCH * 2))
                      + (uint32_t)((lane >> 4) * 16);

    const uint4* src = reinterpret_cast<const uint4*>(fb + (size_t)idx * 2 * CIN);
#pragma unroll
    for (int c = 0; c < ACH; c++) sts128(my_sts + c * 16u, __ldg(src + c));
    __syncwarp();

    const uint2* Bk = reinterpret_cast<const uint2*>(blobtap);
    float acc[2][NT][4];
#pragma unroll
    for (int rt = 0; rt < 2; rt++)
#pragma unroll
        for (int nt = 0; nt < NT; nt++)
#pragma unroll
            for (int j = 0; j < 4; j++) acc[rt][nt][j] = 0.f;

#pragma unroll
    for (int g = 0; g < NK; g++) {
        uint32_t a0h[4], a0l[4], a1h[4], a1l[4];
        ldm_x4(a0h, ldm_base + (uint32_t)(g * 32));
        ldm_x4(a0l, ldm_base + (uint32_t)(CIN * 2 + g * 32));
        ldm_x4(a1h, ldm_base + (uint32_t)(16 * (PITCH * 2) + g * 32));
        ldm_x4(a1l, ldm_base + (uint32_t)(16 * (PITCH * 2) + CIN * 2 + g * 32));
#pragma unroll
        for (int nt = 0; nt < NT; nt++) {
            uint2 bh = __ldg(&Bk[((g)      * NT + nt) * 32 + lane]);
            uint2 bl = __ldg(&Bk[((NK + g) * NT + nt) * 32 + lane]);
            mma16816(acc[0][nt], a0h, bh);
            mma16816(acc[0][nt], a0h, bl);
            mma16816(acc[0][nt], a0l, bh);
            mma16816(acc[1][nt], a1h, bh);
            mma16816(acc[1][nt], a1h, bl);
            mma16816(acc[1][nt], a1l, bh);
        }
    }

    int gid = lane >> 2, t = lane & 3;
#pragma unroll
    for (int rt = 0; rt < 2; rt++) {
        int r0 = row0 + w * 32 + rt * 16 + gid;
#pragma unroll
        for (int nt = 0; nt < NT; nt++) {
            int cbase = nt * 8 + 2 * t;
            if (r0 < rows)
                *reinterpret_cast<float2*>(&out[(size_t)r0 * COUT + cbase]) =
                    make_float2(acc[rt][nt][0], acc[rt][nt][1]);
            if (r0 + 8 < rows)
                *reinterpret_cast<float2*>(&out[(size_t)(r0 + 8) * COUT + cbase]) =
                    make_float2(acc[rt][nt][2], acc[rt][nt][3]);
        }
    }
}

// ---------------------------------------------------------------------------
// Compacted-pair conv: persistent warps over 16-pair groups (tap-major),
// bf16-split MMA, atomicAdd accumulation into out (spread-address REDG).
// ---------------------------------------------------------------------------
template <int CIN, int COUT>
__global__ __launch_bounds__(256, 2)
void conv_pairs(const __nv_bfloat16* __restrict__ fb,
                const uint8_t* __restrict__ blob,
                float* __restrict__ out,
                const int* __restrict__ pm, const int* __restrict__ pi,
                const int* __restrict__ cnt, const int* __restrict__ goff,
                const int* __restrict__ totg, int ntaps, int P) {
    constexpr int NK = CIN / 16;
    constexpr int NT = COUT / 8;
    constexpr int PITCH2 = (2 * CIN + 8) * 2;   // bytes per staged row
    constexpr int BSTRu2 = 2 * NK * NT * 32;    // uint2 per tap blob

    __shared__ __align__(16) uint8_t As[8][16 * PITCH2];
    __shared__ int s_m[8][16];
    __shared__ int s_goff[28], s_cnt[28];

    int tid = threadIdx.x;
    int w = tid >> 5, lane = tid & 31;
    if (tid <= ntaps) s_goff[tid] = goff[tid];
    if (tid < ntaps) s_cnt[tid] = cnt[tid];
    __syncthreads();

    int TG = totg[0];
    uint32_t abase = smem_u32(As[w]);
    uint32_t ldm_base = abase + (uint32_t)((lane & 15) * PITCH2) +
                        (uint32_t)((lane >> 4) * 16);
    const uint2* Bb = reinterpret_cast<const uint2*>(blob);
    int r = lane & 15, h = lane >> 4;

    for (int g = blockIdx.x * 8 + w; g < TG; g += gridDim.x * 8) {
        // find tap k: goff[k] <= g < goff[k+1]
        int klo = 0, khi = ntaps;
        while (khi - klo > 1) {
            int mid = (klo + khi) >> 1;
            if (g >= s_goff[mid]) klo = mid; else khi = mid;
        }
        int k = klo;
        int slot = (g - s_goff[k]) * 16 + r;
        bool valid = slot < s_cnt[k];
        int m = -1, idx = P;
        if (valid) {
            m   = __ldg(&pm[k * NMAX + slot]);
            idx = __ldg(&pi[k * NMAX + slot]);
        }
        if (h == 0) s_m[w][r] = valid ? m : -1;

        // stage 16 rows: lane (r, h) copies half h of row r
        const uint4* src = reinterpret_cast<const uint4*>(fb) +
                           (size_t)idx * (CIN / 4) + h * (CIN / 8);
        uint32_t dst = abase + (uint32_t)(r * PITCH2 + h * (2 * CIN));
#pragma unroll
        for (int c = 0; c < CIN / 8; c++) sts128(dst + c * 16u, __ldg(src + c));
        __syncwarp();

        const uint2* Bk = Bb + (size_t)k * BSTRu2;
        float acc[NT][4];
#pragma unroll
        for (int nt = 0; nt < NT; nt++)
#pragma unroll
            for (int j = 0; j < 4; j++) acc[nt][j] = 0.f;

#pragma unroll
        for (int g2 = 0; g2 < NK; g2++) {
            uint32_t ah[4], al[4];
            ldm_x4(ah, ldm_base + (uint32_t)(g2 * 32));
            ldm_x4(al, ldm_base + (uint32_t)(CIN * 2 + g2 * 32));
#pragma unroll
            for (int nt = 0; nt < NT; nt++) {
                uint2 bh = __ldg(&Bk[((g2)      * NT + nt) * 32 + lane]);
                uint2 bl = __ldg(&Bk[((NK + g2) * NT + nt) * 32 + lane]);
                mma16816(acc[nt], ah, bh);
                mma16816(acc[nt], ah, bl);
                mma16816(acc[nt], al, bh);
            }
        }

        int gid = lane >> 2, t = lane & 3;
        int m0 = s_m[w][gid], m1 = s_m[w][gid + 8];
#pragma unroll
        for (int nt = 0; nt < NT; nt++) {
            int cb = nt * 8 + 2 * t;
            if (m0 >= 0) {
                atomicAdd(&out[(size_t)m0 * COUT + cb],     acc[nt][0]);
                atomicAdd(&out[(size_t)m0 * COUT + cb + 1], acc[nt][1]);
            }
            if (m1 >= 0) {
                atomicAdd(&out[(size_t)m1 * COUT + cb],     acc[nt][2]);
                atomicAdd(&out[(size_t)m1 * COUT + cb + 1], acc[nt][3]);
            }
        }
        __syncwarp();
    }
}

// ---------------------------------------------------------------------------
// Stride-2 transpose conv (deconv): out[n] = g[up_cidx[n]] @ W[up_k[n]]
// ---------------------------------------------------------------------------
__global__ __launch_bounds__(256) void deconv_kernel(const float* __restrict__ g,
                                                     const int* __restrict__ up_cidx,
                                                     const int* __restrict__ up_k,
                                                     const float* __restrict__ Wup,
                                                     float* __restrict__ out,
                                                     int nrows, int kbase) {
    __shared__ float Ws[4][64][32];  // 32 KB
    int tid = threadIdx.x;
    const float4* src = reinterpret_cast<const float4*>(Wup + (size_t)kbase * 64 * 32);
    for (int v = tid; v < 4 * 64 * 32 / 4; v += 256)
        reinterpret_cast<float4*>(&Ws[0][0][0])[v] = src[v];
    __syncthreads();

    int warp = tid >> 5, lane = tid & 31;
    int base = blockIdx.x * 64 + warp * 8;
#pragma unroll
    for (int i = 0; i < 8; i++) {
        int row = base + i;
        if (row >= nrows) break;
        int k = up_k[row] - kbase;
        if ((unsigned)k < 4u) {
            int cid = up_cidx[row];
            const float* grow = g + (size_t)cid * 64;
            float xa = grow[lane], xb = grow[lane + 32];
            float acc = 0.f;
#pragma unroll
            for (int cin = 0; cin < 64; cin++) {
                float xv = __shfl_sync(0xFFFFFFFFu, (cin < 32) ? xa : xb, cin & 31);
                acc = fmaf(xv, Ws[k][cin][lane], acc);
            }
            out[(size_t)row * 32 + lane] = acc;
        }
    }
}

// ---------------------------------------------------------------------------
// Host launcher
// ---------------------------------------------------------------------------
static void* sym_addr(const void* s) {
    void* p = nullptr;
    cudaGetSymbolAddress(&p, s);
    return p;
}

template <int CIN>
static constexpr int center_smem() {
    return 256 * (2 * CIN + 8) * 2;
}

extern "C" void kernel_launch(void* const* d_in, const int* in_sizes, int n_in,
                              void* d_out, int out_size) {
    const float* feat    = (const float*)d_in[0];
    const float* w_sub1  = (const float*)d_in[1];
    const float* w_down  = (const float*)d_in[2];
    const float* w_sub2  = (const float*)d_in[3];
    const float* w_up    = (const float*)d_in[4];
    const float* w_sub3  = (const float*)d_in[5];
    const float* g1 = (const float*)d_in[6];  const float* b1 = (const float*)d_in[7];
    const float* g2 = (const float*)d_in[8];  const float* b2 = (const float*)d_in[9];
    const float* g3 = (const float*)d_in[10]; const float* b3 = (const float*)d_in[11];
    const float* g4 = (const float*)d_in[12]; const float* b4 = (const float*)d_in[13];
    const float* g5 = (const float*)d_in[14]; const float* b5 = (const float*)d_in[15];
    const int* nbr_fine   = (const int*)d_in[16];
    const int* nbr_coarse = (const int*)d_in[17];
    const int* down_idx   = (const int*)d_in[18];
    const int* up_cidx    = (const int*)d_in[19];
    const int* up_k       = (const int*)d_in[20];

    int N = in_sizes[0] / 32;
    int M = in_sizes[18] / 8;

    __nv_bfloat16* t0b = (__nv_bfloat16*)sym_addr(g_t0b);
    __nv_bfloat16* t1b = (__nv_bfloat16*)sym_addr(g_t1b);
    __nv_bfloat16* t2b = (__nv_bfloat16*)sym_addr(g_t2b);
    __nv_bfloat16* t4b = (__nv_bfloat16*)sym_addr(g_t4b);
    float*  x1   = (float*)sym_addr(g_x1);
    float*  xc0  = (float*)sym_addr(g_xc0);
    float*  xc1  = (float*)sym_addr(g_xc1);
    float*  t3   = (float*)sym_addr(g_t3);
    float*  xf   = (float*)sym_addr(g_xf);
    double* part = (double*)sym_addr(g_part);
    float*  sc   = (float*)sym_addr(g_scale);
    float*  sh   = (float*)sym_addr(g_shift);
    uint8_t* wb1 = (uint8_t*)sym_addr(g_wb1);
    uint8_t* wbD = (uint8_t*)sym_addr(g_wbD);
    uint8_t* wb2 = (uint8_t*)sym_addr(g_wb2);
    uint8_t* wb3 = (uint8_t*)sym_addr(g_wb3);
    int* cntF = (int*)sym_addr(g_cntF); int* goffF = (int*)sym_addr(g_goffF);
    int* totF = (int*)sym_addr(g_totF);
    int* pmF  = (int*)sym_addr(g_pmF);  int* piF  = (int*)sym_addr(g_piF);
    int* cntC = (int*)sym_addr(g_cntC); int* goffC = (int*)sym_addr(g_goffC);
    int* totC = (int*)sym_addr(g_totC);
    int* pmC  = (int*)sym_addr(g_pmC);  int* piC  = (int*)sym_addr(g_piC);
    float*  outp = (float*)d_out;

    auto cdiv = [](int a, int b) { return (a + b - 1) / b; };

    cudaFuncSetAttribute((const void*)gemm_center<32, 32>,
                         cudaFuncAttributeMaxDynamicSharedMemorySize, center_smem<32>());
    cudaFuncSetAttribute((const void*)gemm_center<64, 64>,
                         cudaFuncAttributeMaxDynamicSharedMemorySize, center_smem<64>());
    cudaFuncSetAttribute((const void*)gemm_center<64, 32>,
                         cudaFuncAttributeMaxDynamicSharedMemorySize, center_smem<64>());

    // W fragment prep
    wprep<32, 32, 27><<<cdiv(27 * 32 * 32, 256), 256>>>(w_sub1, wb1);
    wprep<32, 64, 8><<<cdiv(8 * 32 * 64, 256), 256>>>(w_down, wbD);
    wprep<64, 64, 27><<<cdiv(27 * 64 * 64, 256), 256>>>(w_sub2, wb2);
    wprep<64, 32, 27><<<cdiv(27 * 64 * 32, 256), 256>>>(w_sub3, wb3);

    const int PAIR_GRID = 592;

    // stage 1: BN1(feat) -> t0b ; sub1 = center GEMM + compacted pairs -> x1
    bn_stats1<32><<<NBLK_STATS, 256>>>(feat, N, part);
    bn_stats2<<<1, 64>>>(part, NBLK_STATS, N, g1, b1, sc + 0 * 64, sh + 0 * 64, 32);
    bn_apply_split<32><<<cdiv(N * 8, 256), 256>>>(feat, t0b, sc + 0 * 64, sh + 0 * 64, N);
    pair_reset<<<1, 32>>>(cntF);
    pair_build<<<cdiv(N, 256), 256>>>(nbr_fine, N, N, 27, 13, cntF, pmF, piF);
    pair_scan<<<1, 32>>>(cntF, goffF, totF, 27);
    gemm_center<32, 32><<<cdiv(N, 256), 256, center_smem<32>()>>>(
        t0b, wb1 + 13 * 4096, x1, N, N);
    conv_pairs<32, 32><<<PAIR_GRID, 256>>>(t0b, wb1, x1, pmF, piF,
                                           cntF, goffF, totF, 27, N);

    // stage 2: BN2(x1) -> t1b ; down via rulebook (no center tap) -> xc0
    bn_stats1<32><<<NBLK_STATS, 256>>>(x1, N, part);
    bn_stats2<<<1, 64>>>(part, NBLK_STATS, N, g2, b2, sc + 1 * 64, sh + 1 * 64, 32);
    bn_apply_split<32><<<cdiv(N * 8, 256), 256>>>(x1, t1b, sc + 1 * 64, sh + 1 * 64, N);
    pair_reset<<<1, 32>>>(cntC);
    pair_build<<<cdiv(M, 256), 256>>>(down_idx, M, N, 8, -1, cntC, pmC, piC);
    pair_scan<<<1, 32>>>(cntC, goffC, totC, 8);
    zero_f<<<cdiv(M * 16, 256), 256>>>(xc0, M * 16);
    conv_pairs<32, 64><<<PAIR_GRID, 256>>>(t1b, wbD, xc0, pmC, piC,
                                           cntC, goffC, totC, 8, N);

    // stage 3: BN3(xc0) -> t2b ; sub2 = center GEMM + pairs -> xc1
    bn_stats1<64><<<NBLK_STATS, 256>>>(xc0, M, part);
    bn_stats2<<<1, 64>>>(part, NBLK_STATS, M, g3, b3, sc + 2 * 64, sh + 2 * 64, 64);
    bn_apply_split<64><<<cdiv(M * 16, 256), 256>>>(xc0, t2b, sc + 2 * 64, sh + 2 * 64, M);
    pair_reset<<<1, 32>>>(cntC);
    pair_build<<<cdiv(M, 256), 256>>>(nbr_coarse, M, M, 27, 13, cntC, pmC, piC);
    pair_scan<<<1, 32>>>(cntC, goffC, totC, 27);
    gemm_center<64, 64><<<cdiv(M, 256), 256, center_smem<64>()>>>(
        t2b, wb2 + 13 * 16384, xc1, M, M);
    conv_pairs<64, 64><<<PAIR_GRID, 256>>>(t2b, wb2, xc1, pmC, piC,
                                           cntC, goffC, totC, 27, M);

    // stage 4: BN4(xc1) -> t3 (fp32) ; deconv -> xf
    bn_stats1<64><<<NBLK_STATS, 256>>>(xc1, M, part);
    bn_stats2<<<1, 64>>>(part, NBLK_STATS, M, g4, b4, sc + 3 * 64, sh + 3 * 64, 64);
    bn_apply<64><<<cdiv(M * 16, 256), 256>>>(xc1, t3, sc + 3 * 64, sh + 3 * 64, M);
    deconv_kernel<<<cdiv(N, 64), 256>>>(t3, up_cidx, up_k, w_up, xf, N, 0);
    deconv_kernel<<<cdiv(N, 64), 256>>>(t3, up_cidx, up_k, w_up, xf, N, 4);

    // stage 5: BN5(concat(x1, xf)) -> t4b ; sub3 = center GEMM + pairs -> out
    // (fine rulebook from stage 1 is intact: stages 2-3 used the C set)
    bn_stats1<32><<<NBLK_STATS, 256>>>(x1, N, part);
    bn_stats2<<<1, 64>>>(part, NBLK_STATS, N, g5, b5, sc + 4 * 64, sh + 4 * 64, 32);
    bn_stats1<32><<<NBLK_STATS, 256>>>(xf, N, part);
    bn_stats2<<<1, 64>>>(part, NBLK_STATS, N, g5 + 32, b5 + 32,
                         sc + 4 * 64 + 32, sh + 4 * 64 + 32, 32);
    bn_apply_cat_split<<<cdiv(N * 16, 256), 256>>>(x1, xf, t4b,
                                                   sc + 4 * 64, sh + 4 * 64, N);
    gemm_center<64, 32><<<cdiv(N, 256), 256, center_smem<64>()>>>(
        t4b, wb3 + 13 * 8192, outp, N, N);
    conv_pairs<64, 32><<<PAIR_GRID, 256>>>(t4b, wb3, outp, pmF, piF,
                                           cntF, goffF, totF, 27, N);
}

// round 11
// speedup vs baseline: 1.3832x; 1.3832x over previous
#include <cuda_runtime.h>
#include <cuda_bf16.h>
#include <cstdint>
#include <cstdio>

// ---------------------------------------------------------------------------
// Problem constants
// ---------------------------------------------------------------------------
#define NMAX 200192        // >= N (=200000) and >= M
#define NBLK_STATS 240
#define BN_EPS 1e-4

// ---------------------------------------------------------------------------
// Static device scratch
// ---------------------------------------------------------------------------
__device__ __nv_bfloat16 g_t0b[(NMAX + 1) * 64];    // bn1 split [hi32|lo32]
__device__ float         g_x1[NMAX * 32];           // sub1 out (skip)
__device__ __nv_bfloat16 g_t1b[(NMAX + 1) * 64];    // bn2 split
__device__ float         g_xc0[NMAX * 64];          // down out
__device__ __nv_bfloat16 g_t2b[(NMAX + 1) * 128];   // bn3 split [hi64|lo64]
__device__ float         g_xc1[NMAX * 64];          // sub2 out
__device__ float         g_t3[(NMAX + 1) * 64];     // bn4 fp32 (deconv input)
__device__ float         g_xf[NMAX * 32];           // deconv out
__device__ __nv_bfloat16 g_t4b[(NMAX + 1) * 128];   // bn5(concat) split
__device__ double        g_part[NBLK_STATS * 128];
__device__ float         g_scale[5 * 64];
__device__ float         g_shift[5 * 64];

// Pre-baked B fragment blobs: per tap, [2*NK ksteps (hi then lo)][NT][32 lanes][uint2]
__device__ __align__(16) uint8_t g_wb1[27 * 4096];    // sub1  (32->32)
__device__ __align__(16) uint8_t g_wbD[8 * 8192];     // down  (32->64)
__device__ __align__(16) uint8_t g_wb2[27 * 16384];   // sub2  (64->64)
__device__ __align__(16) uint8_t g_wb3[27 * 8192];    // sub3  (64->32)

// ---------------------------------------------------------------------------
// MMA helpers (sm_80-era PTX; compiles for plain compute_103)
// ---------------------------------------------------------------------------
__device__ __forceinline__ uint32_t smem_u32(const void* p) {
    return (uint32_t)__cvta_generic_to_shared(p);
}
__device__ __forceinline__ void ldm_x4(uint32_t r[4], uint32_t addr) {
    asm volatile("ldmatrix.sync.aligned.m8n8.x4.shared.b16 {%0,%1,%2,%3}, [%4];"
                 : "=r"(r[0]), "=r"(r[1]), "=r"(r[2]), "=r"(r[3]) : "r"(addr));
}
__device__ __forceinline__ void mma16816(float* d, const uint32_t* a, uint2 b) {
    asm volatile(
        "mma.sync.aligned.m16n8k16.row.col.f32.bf16.bf16.f32 "
        "{%0,%1,%2,%3}, {%4,%5,%6,%7}, {%8,%9}, {%0,%1,%2,%3};"
        : "+f"(d[0]), "+f"(d[1]), "+f"(d[2]), "+f"(d[3])
        : "r"(a[0]), "r"(a[1]), "r"(a[2]), "r"(a[3]), "r"(b.x), "r"(b.y));
}
__device__ __forceinline__ void sts128(uint32_t addr, uint4 v) {
    asm volatile("st.shared.v4.b32 [%0], {%1,%2,%3,%4};"
                 :: "r"(addr), "r"(v.x), "r"(v.y), "r"(v.z), "r"(v.w));
}

// ---------------------------------------------------------------------------
// BN stats pass 1: deterministic per-block partial sums (double)
// ---------------------------------------------------------------------------
template <int C>
__global__ __launch_bounds__(256) void bn_stats1(const float* __restrict__ x,
                                                 int rows,
                                                 double* __restrict__ partial) {
    __shared__ double ss[256], sq[256];
    int tid = threadIdx.x;
    long long total = (long long)rows * C;
    double s = 0.0, q = 0.0;
    for (long long i = (long long)blockIdx.x * 256 + tid; i < total;
         i += (long long)gridDim.x * 256) {
        double v = (double)x[i];
        s += v;
        q += v * v;
    }
    ss[tid] = s;
    sq[tid] = q;
    for (int st = 128; st >= C; st >>= 1) {
        __syncthreads();
        if (tid < st) { ss[tid] += ss[tid + st]; sq[tid] += sq[tid + st]; }
    }
    if (tid < C) {
        partial[blockIdx.x * 128 + tid]      = ss[tid];
        partial[blockIdx.x * 128 + 64 + tid] = sq[tid];
    }
}

__global__ void bn_stats2(const double* __restrict__ partial, int nblk, int rows,
                          const float* __restrict__ g, const float* __restrict__ b,
                          float* __restrict__ sc, float* __restrict__ sh, int C) {
    int c = threadIdx.x;
    if (c >= C) return;
    double s = 0.0, q = 0.0;
    for (int i = 0; i < nblk; i++) {
        s += partial[i * 128 + c];
        q += partial[i * 128 + 64 + c];
    }
    double mean = s / rows;
    double var  = q / rows - mean * mean;
    double inv  = 1.0 / sqrt(var + BN_EPS);
    double scale = (double)g[c] * inv;
    sc[c] = (float)scale;
    sh[c] = (float)((double)b[c] - mean * scale);
}

// ---------------------------------------------------------------------------
// BN apply + ReLU + bf16 hi/lo split: y [rows+1][2C] bf16 = [hi(C) | lo(C)]
// ---------------------------------------------------------------------------
__device__ __forceinline__ void split4(float4 d, uint2& hi, uint2& lo) {
    __nv_bfloat16 h0 = __float2bfloat16(d.x), h1 = __float2bfloat16(d.y);
    __nv_bfloat16 h2 = __float2bfloat16(d.z), h3 = __float2bfloat16(d.w);
    __nv_bfloat16 l0 = __float2bfloat16(d.x - __bfloat162float(h0));
    __nv_bfloat16 l1 = __float2bfloat16(d.y - __bfloat162float(h1));
    __nv_bfloat16 l2 = __float2bfloat16(d.z - __bfloat162float(h2));
    __nv_bfloat16 l3 = __float2bfloat16(d.w - __bfloat162float(h3));
    hi.x = ((uint32_t)__bfloat16_as_ushort(h1) << 16) | __bfloat16_as_ushort(h0);
    hi.y = ((uint32_t)__bfloat16_as_ushort(h3) << 16) | __bfloat16_as_ushort(h2);
    lo.x = ((uint32_t)__bfloat16_as_ushort(l1) << 16) | __bfloat16_as_ushort(l0);
    lo.y = ((uint32_t)__bfloat16_as_ushort(l3) << 16) | __bfloat16_as_ushort(l2);
}

template <int C>
__global__ __launch_bounds__(256) void bn_apply_split(const float* __restrict__ x,
                                                      __nv_bfloat16* __restrict__ y,
                                                      const float* __restrict__ sc,
                                                      const float* __restrict__ sh,
                                                      int rows) {
    int i = blockIdx.x * blockDim.x + threadIdx.x;
    if (i < C / 4) {
        uint2 z = make_uint2(0, 0);
        *reinterpret_cast<uint2*>(&y[(size_t)rows * 2 * C + 4 * i]) = z;
        *reinterpret_cast<uint2*>(&y[(size_t)rows * 2 * C + C + 4 * i]) = z;
    }
    int n4 = rows * C / 4;
    if (i < n4) {
        float4 d = reinterpret_cast<const float4*>(x)[i];
        int row = i / (C / 4);
        int c0 = (i % (C / 4)) * 4;
        d.x = fmaxf(fmaf(d.x, __ldg(&sc[c0 + 0]), __ldg(&sh[c0 + 0])), 0.f);
        d.y = fmaxf(fmaf(d.y, __ldg(&sc[c0 + 1]), __ldg(&sh[c0 + 1])), 0.f);
        d.z = fmaxf(fmaf(d.z, __ldg(&sc[c0 + 2]), __ldg(&sh[c0 + 2])), 0.f);
        d.w = fmaxf(fmaf(d.w, __ldg(&sc[c0 + 3]), __ldg(&sh[c0 + 3])), 0.f);
        uint2 hi, lo;
        split4(d, hi, lo);
        *reinterpret_cast<uint2*>(&y[(size_t)row * 2 * C + c0]) = hi;
        *reinterpret_cast<uint2*>(&y[(size_t)row * 2 * C + C + c0]) = lo;
    }
}

// BN apply fp32 (for deconv input), pad row zeroed
template <int C>
__global__ __launch_bounds__(256) void bn_apply(const float* __restrict__ x,
                                                float* __restrict__ y,
                                                const float* __restrict__ sc,
                                                const float* __restrict__ sh,
                                                int rows) {
    int i = blockIdx.x * blockDim.x + threadIdx.x;
    if (i < C / 4) {
        *reinterpret_cast<float4*>(&y[(size_t)rows * C + 4 * i]) =
            make_float4(0.f, 0.f, 0.f, 0.f);
    }
    int n4 = rows * C / 4;
    if (i < n4) {
        float4 d = reinterpret_cast<const float4*>(x)[i];
        int c0 = (i * 4) % C;
        d.x = fmaxf(fmaf(d.x, __ldg(&sc[c0 + 0]), __ldg(&sh[c0 + 0])), 0.f);
        d.y = fmaxf(fmaf(d.y, __ldg(&sc[c0 + 1]), __ldg(&sh[c0 + 1])), 0.f);
        d.z = fmaxf(fmaf(d.z, __ldg(&sc[c0 + 2]), __ldg(&sh[c0 + 2])), 0.f);
        d.w = fmaxf(fmaf(d.w, __ldg(&sc[c0 + 3]), __ldg(&sh[c0 + 3])), 0.f);
        reinterpret_cast<float4*>(y)[i] = d;
    }
}

// BN apply + split for concat(x1[:,:32], xf[:,:32]) -> y [rows+1][128] bf16
__global__ __launch_bounds__(256) void bn_apply_cat_split(const float* __restrict__ x1,
                                                          const float* __restrict__ xf,
                                                          __nv_bfloat16* __restrict__ y,
                                                          const float* __restrict__ sc,
                                                          const float* __restrict__ sh,
                                                          int rows) {
    int i = blockIdx.x * blockDim.x + threadIdx.x;
    if (i < 16) {
        uint2 z = make_uint2(0, 0);
        *reinterpret_cast<uint2*>(&y[(size_t)rows * 128 + 4 * i]) = z;
        *reinterpret_cast<uint2*>(&y[(size_t)rows * 128 + 64 + 4 * i]) = z;
    }
    int n4 = rows * 16;
    if (i < n4) {
        int row = i / 16, q = i % 16;
        float4 d = (q < 8) ? reinterpret_cast<const float4*>(x1)[row * 8 + q]
                           : reinterpret_cast<const float4*>(xf)[row * 8 + (q - 8)];
        int c0 = q * 4;
        d.x = fmaxf(fmaf(d.x, __ldg(&sc[c0 + 0]), __ldg(&sh[c0 + 0])), 0.f);
        d.y = fmaxf(fmaf(d.y, __ldg(&sc[c0 + 1]), __ldg(&sh[c0 + 1])), 0.f);
        d.z = fmaxf(fmaf(d.z, __ldg(&sc[c0 + 2]), __ldg(&sh[c0 + 2])), 0.f);
        d.w = fmaxf(fmaf(d.w, __ldg(&sc[c0 + 3]), __ldg(&sh[c0 + 3])), 0.f);
        uint2 hi, lo;
        split4(d, hi, lo);
        *reinterpret_cast<uint2*>(&y[(size_t)row * 128 + c0]) = hi;
        *reinterpret_cast<uint2*>(&y[(size_t)row * 128 + 64 + c0]) = lo;
    }
}

// ---------------------------------------------------------------------------
// W prep: bake B fragments for mma.sync m16n8k16 (col-major B = W^T view).
// ---------------------------------------------------------------------------
template <int CIN, int COUT, int K>
__global__ void wprep(const float* __restrict__ W, uint8_t* __restrict__ blob) {
    constexpr int NK = CIN / 16;
    constexpr int NT = COUT / 8;
    constexpr int BBYTES = 2 * NK * NT * 32 * 8;
    int i = blockIdx.x * blockDim.x + threadIdx.x;
    if (i >= K * CIN * COUT) return;
    int k = i / (CIN * COUT);
    int r = i % (CIN * COUT);
    int ci = r / COUT, co = r % COUT;
    float w = W[i];
    __nv_bfloat16 hi = __float2bfloat16(w);
    __nv_bfloat16 lo = __float2bfloat16(w - __bfloat162float(hi));

    int ksg  = ci >> 4;
    int kloc = ci & 15;
    int reg  = kloc >> 3;
    int kl   = kloc & 7;
    int t    = kl >> 1;
    int half = kl & 1;
    int nt   = co >> 3;
    int gid  = co & 7;
    int lane = gid * 4 + t;

    uint8_t* base = blob + (size_t)k * BBYTES;
    size_t off_hi = ((size_t)(ksg * NT + nt) * 32 + lane) * 8 + reg * 4 + half * 2;
    size_t off_lo = ((size_t)((NK + ksg) * NT + nt) * 32 + lane) * 8 + reg * 4 + half * 2;
    *reinterpret_cast<__nv_bfloat16*>(base + off_hi) = hi;
    *reinterpret_cast<__nv_bfloat16*>(base + off_lo) = lo;
}

// ---------------------------------------------------------------------------
// Warp-autonomous sparsity-aware conv, 16 rows/warp (mma.sync, bf16 split).
// CTA = 256 thr = 8 warps = 128 rows. All warps walk taps in phase (keeps the
// 16KB tap B-blob L1-resident across the CTA). Per warp-tap:
// ballot(16 rows) -> skip if empty; 2 lanes/row gather halves; one
// ldmatrix.x4 pair + 3*NT mma. No block barriers.
// ---------------------------------------------------------------------------
template <int CIN, int COUT, int K, int MINBLK>
__global__ __launch_bounds__(256, MINBLK)
void conv_mma16(const __nv_bfloat16* __restrict__ fb,   // [P+1][2*CIN] hi|lo
                const int* __restrict__ nbr,
                const uint8_t* __restrict__ blob,
                float* __restrict__ out,
                int rows, int P) {
    constexpr int NK = CIN / 16;              // ksteps per pass
    constexpr int NT = COUT / 8;              // n tiles
    constexpr int PITCH2 = (2 * CIN + 8) * 2; // bytes per A row (+16B pad)
    constexpr int HCH = CIN / 8;              // uint4 per half-row
    constexpr int BSTR = 2 * NK * NT * 32;    // uint2 per tap blob

    __shared__ __align__(16) uint8_t As[8][16 * PITCH2];

    int tid = threadIdx.x;
    int w = tid >> 5, lane = tid & 31;
    int r = lane & 15, h = lane >> 4;
    int row0 = blockIdx.x * 128;

    int myrow = row0 + w * 16 + r;
    bool gv = (myrow < rows);

    uint32_t abase = smem_u32(As[w]);
    uint32_t my_sts = abase + (uint32_t)(r * PITCH2 + h * (2 * CIN));
    uint32_t ldm_base = abase + (uint32_t)(r * PITCH2 + h * 16);

    const uint2* Bblob = reinterpret_cast<const uint2*>(blob);

    float acc[NT][4];
#pragma unroll
    for (int nt = 0; nt < NT; nt++)
#pragma unroll
        for (int j = 0; j < 4; j++) acc[nt][j] = 0.f;

    int idx_nxt = gv ? __ldg(&nbr[0 * (size_t)rows + myrow]) : P;

#pragma unroll 1
    for (int k = 0; k < K; k++) {
        int idx = idx_nxt;
        if (k + 1 < K)
            idx_nxt = gv ? __ldg(&nbr[(size_t)(k + 1) * rows + myrow]) : P;

        unsigned pres = __ballot_sync(0xFFFFFFFFu, idx != P) & 0xFFFFu;
        if (pres == 0) continue;                 // warp-tap skip (exact)

        // gather: lane (r, h) loads half h of row r (sentinel -> zero pad row)
        const uint4* src = reinterpret_cast<const uint4*>(
            fb + (size_t)idx * 2 * CIN) + h * HCH;
#pragma unroll
        for (int c = 0; c < HCH; c++) sts128(my_sts + c * 16u, __ldg(src + c));
        __syncwarp();

        const uint2* Bk = Bblob + (size_t)k * BSTR;
#pragma unroll
        for (int g = 0; g < NK; g++) {
            uint32_t ah[4], al[4];
            ldm_x4(ah, ldm_base + (uint32_t)(g * 32));
            ldm_x4(al, ldm_base + (uint32_t)(CIN * 2 + g * 32));
#pragma unroll
            for (int nt = 0; nt < NT; nt++) {
                uint2 bh = __ldg(&Bk[((g)      * NT + nt) * 32 + lane]);
                uint2 bl = __ldg(&Bk[((NK + g) * NT + nt) * 32 + lane]);
                mma16816(acc[nt], ah, bh);
                mma16816(acc[nt], ah, bl);
                mma16816(acc[nt], al, bh);
            }
        }
        __syncwarp();
    }

    // epilogue: m16n8 fragment -> rows gid and gid+8
    int gid = lane >> 2, t = lane & 3;
    int r0 = row0 + w * 16 + gid;
#pragma unroll
    for (int nt = 0; nt < NT; nt++) {
        int cbase = nt * 8 + 2 * t;
        if (r0 < rows)
            *reinterpret_cast<float2*>(&out[(size_t)r0 * COUT + cbase]) =
                make_float2(acc[nt][0], acc[nt][1]);
        if (r0 + 8 < rows)
            *reinterpret_cast<float2*>(&out[(size_t)(r0 + 8) * COUT + cbase]) =
                make_float2(acc[nt][2], acc[nt][3]);
    }
}

// ---------------------------------------------------------------------------
// Stride-2 transpose conv (deconv): out[n] = g[up_cidx[n]] @ W[up_k[n]]
// ---------------------------------------------------------------------------
__global__ __launch_bounds__(256) void deconv_kernel(const float* __restrict__ g,
                                                     const int* __restrict__ up_cidx,
                                                     const int* __restrict__ up_k,
                                                     const float* __restrict__ Wup,
                                                     float* __restrict__ out,
                                                     int nrows, int kbase) {
    __shared__ float Ws[4][64][32];  // 32 KB
    int tid = threadIdx.x;
    const float4* src = reinterpret_cast<const float4*>(Wup + (size_t)kbase * 64 * 32);
    for (int v = tid; v < 4 * 64 * 32 / 4; v += 256)
        reinterpret_cast<float4*>(&Ws[0][0][0])[v] = src[v];
    __syncthreads();

    int warp = tid >> 5, lane = tid & 31;
    int base = blockIdx.x * 64 + warp * 8;
#pragma unroll
    for (int i = 0; i < 8; i++) {
        int row = base + i;
        if (row >= nrows) break;
        int k = up_k[row] - kbase;
        if ((unsigned)k < 4u) {
            int cid = up_cidx[row];
            const float* grow = g + (size_t)cid * 64;
            float xa = grow[lane], xb = grow[lane + 32];
            float acc = 0.f;
#pragma unroll
            for (int cin = 0; cin < 64; cin++) {
                float xv = __shfl_sync(0xFFFFFFFFu, (cin < 32) ? xa : xb, cin & 31);
                acc = fmaf(xv, Ws[k][cin][lane], acc);
            }
            out[(size_t)row * 32 + lane] = acc;
        }
    }
}

// ---------------------------------------------------------------------------
// Host launcher
// ---------------------------------------------------------------------------
static void* sym_addr(const void* s) {
    void* p = nullptr;
    cudaGetSymbolAddress(&p, s);
    return p;
}

extern "C" void kernel_launch(void* const* d_in, const int* in_sizes, int n_in,
                              void* d_out, int out_size) {
    const float* feat    = (const float*)d_in[0];
    const float* w_sub1  = (const float*)d_in[1];
    const float* w_down  = (const float*)d_in[2];
    const float* w_sub2  = (const float*)d_in[3];
    const float* w_up    = (const float*)d_in[4];
    const float* w_sub3  = (const float*)d_in[5];
    const float* g1 = (const float*)d_in[6];  const float* b1 = (const float*)d_in[7];
    const float* g2 = (const float*)d_in[8];  const float* b2 = (const float*)d_in[9];
    const float* g3 = (const float*)d_in[10]; const float* b3 = (const float*)d_in[11];
    const float* g4 = (const float*)d_in[12]; const float* b4 = (const float*)d_in[13];
    const float* g5 = (const float*)d_in[14]; const float* b5 = (const float*)d_in[15];
    const int* nbr_fine   = (const int*)d_in[16];
    const int* nbr_coarse = (const int*)d_in[17];
    const int* down_idx   = (const int*)d_in[18];
    const int* up_cidx    = (const int*)d_in[19];
    const int* up_k       = (const int*)d_in[20];

    int N = in_sizes[0] / 32;
    int M = in_sizes[18] / 8;

    __nv_bfloat16* t0b = (__nv_bfloat16*)sym_addr(g_t0b);
    __nv_bfloat16* t1b = (__nv_bfloat16*)sym_addr(g_t1b);
    __nv_bfloat16* t2b = (__nv_bfloat16*)sym_addr(g_t2b);
    __nv_bfloat16* t4b = (__nv_bfloat16*)sym_addr(g_t4b);
    float*  x1   = (float*)sym_addr(g_x1);
    float*  xc0  = (float*)sym_addr(g_xc0);
    float*  xc1  = (float*)sym_addr(g_xc1);
    float*  t3   = (float*)sym_addr(g_t3);
    float*  xf   = (float*)sym_addr(g_xf);
    double* part = (double*)sym_addr(g_part);
    float*  sc   = (float*)sym_addr(g_scale);
    float*  sh   = (float*)sym_addr(g_shift);
    uint8_t* wb1 = (uint8_t*)sym_addr(g_wb1);
    uint8_t* wbD = (uint8_t*)sym_addr(g_wbD);
    uint8_t* wb2 = (uint8_t*)sym_addr(g_wb2);
    uint8_t* wb3 = (uint8_t*)sym_addr(g_wb3);
    float*  outp = (float*)d_out;

    auto cdiv = [](int a, int b) { return (a + b - 1) / b; };

    // W fragment prep (deterministic, idempotent)
    wprep<32, 32, 27><<<cdiv(27 * 32 * 32, 256), 256>>>(w_sub1, wb1);
    wprep<32, 64, 8><<<cdiv(8 * 32 * 64, 256), 256>>>(w_down, wbD);
    wprep<64, 64, 27><<<cdiv(27 * 64 * 64, 256), 256>>>(w_sub2, wb2);
    wprep<64, 32, 27><<<cdiv(27 * 64 * 32, 256), 256>>>(w_sub3, wb3);

    // stage 1: BN1(feat) -> t0b ; sub1 -> x1
    bn_stats1<32><<<NBLK_STATS, 256>>>(feat, N, part);
    bn_stats2<<<1, 64>>>(part, NBLK_STATS, N, g1, b1, sc + 0 * 64, sh + 0 * 64, 32);
    bn_apply_split<32><<<cdiv(N * 8, 256), 256>>>(feat, t0b, sc + 0 * 64, sh + 0 * 64, N);
    conv_mma16<32, 32, 27, 3><<<cdiv(N, 128), 256>>>(t0b, nbr_fine, wb1, x1, N, N);

    // stage 2: BN2(x1) -> t1b ; down -> xc0
    bn_stats1<32><<<NBLK_STATS, 256>>>(x1, N, part);
    bn_stats2<<<1, 64>>>(part, NBLK_STATS, N, g2, b2, sc + 1 * 64, sh + 1 * 64, 32);
    bn_apply_split<32><<<cdiv(N * 8, 256), 256>>>(x1, t1b, sc + 1 * 64, sh + 1 * 64, N);
    conv_mma16<32, 64, 8, 2><<<cdiv(M, 128), 256>>>(t1b, down_idx, wbD, xc0, M, N);

    // stage 3: BN3(xc0) -> t2b ; sub2 -> xc1
    bn_stats1<64><<<NBLK_STATS, 256>>>(xc0, M, part);
    bn_stats2<<<1, 64>>>(part, NBLK_STATS, M, g3, b3, sc + 2 * 64, sh + 2 * 64, 64);
    bn_apply_split<64><<<cdiv(M * 16, 256), 256>>>(xc0, t2b, sc + 2 * 64, sh + 2 * 64, M);
    conv_mma16<64, 64, 27, 2><<<cdiv(M, 128), 256>>>(t2b, nbr_coarse, wb2, xc1, M, M);

    // stage 4: BN4(xc1) -> t3 (fp32) ; deconv -> xf
    bn_stats1<64><<<NBLK_STATS, 256>>>(xc1, M, part);
    bn_stats2<<<1, 64>>>(part, NBLK_STATS, M, g4, b4, sc + 3 * 64, sh + 3 * 64, 64);
    bn_apply<64><<<cdiv(M * 16, 256), 256>>>(xc1, t3, sc + 3 * 64, sh + 3 * 64, M);
    deconv_kernel<<<cdiv(N, 64), 256>>>(t3, up_cidx, up_k, w_up, xf, N, 0);
    deconv_kernel<<<cdiv(N, 64), 256>>>(t3, up_cidx, up_k, w_up, xf, N, 4);

    // stage 5: BN5(concat(x1, xf)) -> t4b ; sub3 -> out
    bn_stats1<32><<<NBLK_STATS, 256>>>(x1, N, part);
    bn_stats2<<<1, 64>>>(part, NBLK_STATS, N, g5, b5, sc + 4 * 64, sh + 4 * 64, 32);
    bn_stats1<32><<<NBLK_STATS, 256>>>(xf, N, part);
    bn_stats2<<<1, 64>>>(part, NBLK_STATS, N, g5 + 32, b5 + 32,
                         sc + 4 * 64 + 32, sh + 4 * 64 + 32, 32);
    bn_apply_cat_split<<<cdiv(N * 16, 256), 256>>>(x1, xf, t4b,
                                                   sc + 4 * 64, sh + 4 * 64, N);
    conv_mma16<64, 32, 27, 3><<<cdiv(N, 128), 256>>>(t4b, nbr_fine, wb3, outp, N, N);
}

// round 16
// speedup vs baseline: 1.6710x; 1.2081x over previous
#include <cuda_runtime.h>
#include <cuda_bf16.h>
#include <cstdint>
#include <cstdio>

// ---------------------------------------------------------------------------
// Problem constants
// ---------------------------------------------------------------------------
#define NMAX 200192        // >= N (=200000) and >= M
#define NBLK_STATS 240
#define BN_EPS 1e-4

// ---------------------------------------------------------------------------
// Static device scratch
// ---------------------------------------------------------------------------
__device__ __nv_bfloat16 g_t0b[(NMAX + 1) * 64];    // bn1 split [hi32|lo32]
__device__ float         g_x1[NMAX * 32];           // sub1 out (skip)
__device__ __nv_bfloat16 g_t1b[(NMAX + 1) * 64];    // bn2 split
__device__ float         g_xc0[NMAX * 64];          // down out
__device__ __nv_bfloat16 g_t2b[(NMAX + 1) * 128];   // bn3 split [hi64|lo64]
__device__ float         g_xc1[NMAX * 64];          // sub2 out
__device__ float         g_t3[(NMAX + 1) * 64];     // bn4 fp32 (deconv input)
__device__ float         g_xf[NMAX * 32];           // deconv out
__device__ __nv_bfloat16 g_t4b[(NMAX + 1) * 128];   // bn5(concat) split
__device__ float         g_partf[NBLK_STATS * 128];
__device__ int           g_ctr;                     // self-resetting
__device__ float         g_scale[5 * 64];
__device__ float         g_shift[5 * 64];

// Pre-baked B fragment blobs: per tap, [2*NK ksteps (hi then lo)][NT][32 lanes][uint2]
__device__ __align__(16) uint8_t g_wb1[27 * 4096];    // sub1  (32->32)
__device__ __align__(16) uint8_t g_wbD[8 * 8192];     // down  (32->64)
__device__ __align__(16) uint8_t g_wb2[27 * 16384];   // sub2  (64->64)
__device__ __align__(16) uint8_t g_wb3[27 * 8192];    // sub3  (64->32)

// ---------------------------------------------------------------------------
// MMA helpers (sm_80-era PTX; compiles for plain compute_103)
// ---------------------------------------------------------------------------
__device__ __forceinline__ uint32_t smem_u32(const void* p) {
    return (uint32_t)__cvta_generic_to_shared(p);
}
__device__ __forceinline__ void ldm_x4(uint32_t r[4], uint32_t addr) {
    asm volatile("ldmatrix.sync.aligned.m8n8.x4.shared.b16 {%0,%1,%2,%3}, [%4];"
                 : "=r"(r[0]), "=r"(r[1]), "=r"(r[2]), "=r"(r[3]) : "r"(addr));
}
__device__ __forceinline__ void mma16816(float* d, const uint32_t* a, uint2 b) {
    asm volatile(
        "mma.sync.aligned.m16n8k16.row.col.f32.bf16.bf16.f32 "
        "{%0,%1,%2,%3}, {%4,%5,%6,%7}, {%8,%9}, {%0,%1,%2,%3};"
        : "+f"(d[0]), "+f"(d[1]), "+f"(d[2]), "+f"(d[3])
        : "r"(a[0]), "r"(a[1]), "r"(a[2]), "r"(a[3]), "r"(b.x), "r"(b.y));
}
__device__ __forceinline__ void sts128(uint32_t addr, uint4 v) {
    asm volatile("st.shared.v4.b32 [%0], {%1,%2,%3,%4};"
                 :: "r"(addr), "r"(v.x), "r"(v.y), "r"(v.z), "r"(v.w));
}

// ---------------------------------------------------------------------------
// Fused BN stats: fp32 per-block partials + last-block fp64 reduce -> sc/sh.
// Deterministic (fixed-order reduce). Counter self-resets for graph replay.
// ---------------------------------------------------------------------------
template <int C>
__global__ __launch_bounds__(256) void bn_stats_fused(
    const float* __restrict__ x, int rows,
    const float* __restrict__ g, const float* __restrict__ b,
    float* __restrict__ sc, float* __restrict__ sh,
    float* __restrict__ partial, int* __restrict__ ctr) {
    __shared__ float ss[256], sq[256];
    __shared__ int lastflag;
    int tid = threadIdx.x;
    long long total = (long long)rows * C;
    float s = 0.f, q = 0.f;
    for (long long i = (long long)blockIdx.x * 256 + tid; i < total;
         i += (long long)gridDim.x * 256) {
        float v = x[i];
        s += v;
        q += v * v;
    }
    ss[tid] = s;
    sq[tid] = q;
    for (int st = 128; st >= C; st >>= 1) {
        __syncthreads();
        if (tid < st) { ss[tid] += ss[tid + st]; sq[tid] += sq[tid + st]; }
    }
    if (tid < C) {
        partial[blockIdx.x * 128 + tid]      = ss[tid];
        partial[blockIdx.x * 128 + 64 + tid] = sq[tid];
    }
    __threadfence();
    __syncthreads();
    if (tid == 0) lastflag = (atomicAdd(ctr, 1) == (int)gridDim.x - 1) ? 1 : 0;
    __syncthreads();
    if (lastflag) {
        if (tid < C) {
            double S = 0.0, Q = 0.0;
            for (int i2 = 0; i2 < (int)gridDim.x; i2++) {
                S += partial[i2 * 128 + tid];
                Q += partial[i2 * 128 + 64 + tid];
            }
            double mean = S / rows;
            double var  = Q / rows - mean * mean;
            double inv  = 1.0 / sqrt(var + BN_EPS);
            double scale = (double)g[tid] * inv;
            sc[tid] = (float)scale;
            sh[tid] = (float)((double)b[tid] - mean * scale);
        }
        __syncthreads();
        if (tid == 0) *ctr = 0;   // reset for next use / next replay
    }
}

// ---------------------------------------------------------------------------
// BN apply + ReLU + bf16 hi/lo split helpers
// ---------------------------------------------------------------------------
__device__ __forceinline__ void split4(float4 d, uint2& hi, uint2& lo) {
    __nv_bfloat16 h0 = __float2bfloat16(d.x), h1 = __float2bfloat16(d.y);
    __nv_bfloat16 h2 = __float2bfloat16(d.z), h3 = __float2bfloat16(d.w);
    __nv_bfloat16 l0 = __float2bfloat16(d.x - __bfloat162float(h0));
    __nv_bfloat16 l1 = __float2bfloat16(d.y - __bfloat162float(h1));
    __nv_bfloat16 l2 = __float2bfloat16(d.z - __bfloat162float(h2));
    __nv_bfloat16 l3 = __float2bfloat16(d.w - __bfloat162float(h3));
    hi.x = ((uint32_t)__bfloat16_as_ushort(h1) << 16) | __bfloat16_as_ushort(h0);
    hi.y = ((uint32_t)__bfloat16_as_ushort(h3) << 16) | __bfloat16_as_ushort(h2);
    lo.x = ((uint32_t)__bfloat16_as_ushort(l1) << 16) | __bfloat16_as_ushort(l0);
    lo.y = ((uint32_t)__bfloat16_as_ushort(l3) << 16) | __bfloat16_as_ushort(l2);
}

template <int C>
__global__ __launch_bounds__(256) void bn_apply_split(const float* __restrict__ x,
                                                      __nv_bfloat16* __restrict__ y,
                                                      const float* __restrict__ sc,
                                                      const float* __restrict__ sh,
                                                      int rows) {
    int i = blockIdx.x * blockDim.x + threadIdx.x;
    if (i < C / 4) {
        uint2 z = make_uint2(0, 0);
        *reinterpret_cast<uint2*>(&y[(size_t)rows * 2 * C + 4 * i]) = z;
        *reinterpret_cast<uint2*>(&y[(size_t)rows * 2 * C + C + 4 * i]) = z;
    }
    int n4 = rows * C / 4;
    if (i < n4) {
        float4 d = reinterpret_cast<const float4*>(x)[i];
        int row = i / (C / 4);
        int c0 = (i % (C / 4)) * 4;
        d.x = fmaxf(fmaf(d.x, __ldg(&sc[c0 + 0]), __ldg(&sh[c0 + 0])), 0.f);
        d.y = fmaxf(fmaf(d.y, __ldg(&sc[c0 + 1]), __ldg(&sh[c0 + 1])), 0.f);
        d.z = fmaxf(fmaf(d.z, __ldg(&sc[c0 + 2]), __ldg(&sh[c0 + 2])), 0.f);
        d.w = fmaxf(fmaf(d.w, __ldg(&sc[c0 + 3]), __ldg(&sh[c0 + 3])), 0.f);
        uint2 hi, lo;
        split4(d, hi, lo);
        *reinterpret_cast<uint2*>(&y[(size_t)row * 2 * C + c0]) = hi;
        *reinterpret_cast<uint2*>(&y[(size_t)row * 2 * C + C + c0]) = lo;
    }
}

// BN apply fp32 (for deconv input), pad row zeroed
template <int C>
__global__ __launch_bounds__(256) void bn_apply(const float* __restrict__ x,
                                                float* __restrict__ y,
                                                const float* __restrict__ sc,
                                                const float* __restrict__ sh,
                                                int rows) {
    int i = blockIdx.x * blockDim.x + threadIdx.x;
    if (i < C / 4) {
        *reinterpret_cast<float4*>(&y[(size_t)rows * C + 4 * i]) =
            make_float4(0.f, 0.f, 0.f, 0.f);
    }
    int n4 = rows * C / 4;
    if (i < n4) {
        float4 d = reinterpret_cast<const float4*>(x)[i];
        int c0 = (i * 4) % C;
        d.x = fmaxf(fmaf(d.x, __ldg(&sc[c0 + 0]), __ldg(&sh[c0 + 0])), 0.f);
        d.y = fmaxf(fmaf(d.y, __ldg(&sc[c0 + 1]), __ldg(&sh[c0 + 1])), 0.f);
        d.z = fmaxf(fmaf(d.z, __ldg(&sc[c0 + 2]), __ldg(&sh[c0 + 2])), 0.f);
        d.w = fmaxf(fmaf(d.w, __ldg(&sc[c0 + 3]), __ldg(&sh[c0 + 3])), 0.f);
        reinterpret_cast<float4*>(y)[i] = d;
    }
}

// BN apply + split for concat(x1[:,:32], xf[:,:32]) -> y [rows+1][128] bf16
__global__ __launch_bounds__(256) void bn_apply_cat_split(const float* __restrict__ x1,
                                                          const float* __restrict__ xf,
                                                          __nv_bfloat16* __restrict__ y,
                                                          const float* __restrict__ sc,
                                                          const float* __restrict__ sh,
                                                          int rows) {
    int i = blockIdx.x * blockDim.x + threadIdx.x;
    if (i < 16) {
        uint2 z = make_uint2(0, 0);
        *reinterpret_cast<uint2*>(&y[(size_t)rows * 128 + 4 * i]) = z;
        *reinterpret_cast<uint2*>(&y[(size_t)rows * 128 + 64 + 4 * i]) = z;
    }
    int n4 = rows * 16;
    if (i < n4) {
        int row = i / 16, q = i % 16;
        float4 d = (q < 8) ? reinterpret_cast<const float4*>(x1)[row * 8 + q]
                           : reinterpret_cast<const float4*>(xf)[row * 8 + (q - 8)];
        int c0 = q * 4;
        d.x = fmaxf(fmaf(d.x, __ldg(&sc[c0 + 0]), __ldg(&sh[c0 + 0])), 0.f);
        d.y = fmaxf(fmaf(d.y, __ldg(&sc[c0 + 1]), __ldg(&sh[c0 + 1])), 0.f);
        d.z = fmaxf(fmaf(d.z, __ldg(&sc[c0 + 2]), __ldg(&sh[c0 + 2])), 0.f);
        d.w = fmaxf(fmaf(d.w, __ldg(&sc[c0 + 3]), __ldg(&sh[c0 + 3])), 0.f);
        uint2 hi, lo;
        split4(d, hi, lo);
        *reinterpret_cast<uint2*>(&y[(size_t)row * 128 + c0]) = hi;
        *reinterpret_cast<uint2*>(&y[(size_t)row * 128 + 64 + c0]) = lo;
    }
}

// ---------------------------------------------------------------------------
// W prep: bake B fragments for mma.sync m16n8k16 (col-major B = W^T view).
// ---------------------------------------------------------------------------
template <int CIN, int COUT, int K>
__global__ void wprep(const float* __restrict__ W, uint8_t* __restrict__ blob) {
    constexpr int NK = CIN / 16;
    constexpr int NT = COUT / 8;
    constexpr int BBYTES = 2 * NK * NT * 32 * 8;
    int i = blockIdx.x * blockDim.x + threadIdx.x;
    if (i >= K * CIN * COUT) return;
    int k = i / (CIN * COUT);
    int r = i % (CIN * COUT);
    int ci = r / COUT, co = r % COUT;
    float w = W[i];
    __nv_bfloat16 hi = __float2bfloat16(w);
    __nv_bfloat16 lo = __float2bfloat16(w - __bfloat162float(hi));

    int ksg  = ci >> 4;
    int kloc = ci & 15;
    int reg  = kloc >> 3;
    int kl   = kloc & 7;
    int t    = kl >> 1;
    int half = kl & 1;
    int nt   = co >> 3;
    int gid  = co & 7;
    int lane = gid * 4 + t;

    uint8_t* base = blob + (size_t)k * BBYTES;
    size_t off_hi = ((size_t)(ksg * NT + nt) * 32 + lane) * 8 + reg * 4 + half * 2;
    size_t off_lo = ((size_t)((NK + ksg) * NT + nt) * 32 + lane) * 8 + reg * 4 + half * 2;
    *reinterpret_cast<__nv_bfloat16*>(base + off_hi) = hi;
    *reinterpret_cast<__nv_bfloat16*>(base + off_lo) = lo;
}

// ---------------------------------------------------------------------------
// Warp-autonomous sparsity-aware conv, 16 rows/warp (mma.sync, bf16 split).
// CTA = 256 thr = 8 warps = 128 rows; taps walked in phase; ballot skip.
// ---------------------------------------------------------------------------
template <int CIN, int COUT, int K, int MINBLK>
__global__ __launch_bounds__(256, MINBLK)
void conv_mma16(const __nv_bfloat16* __restrict__ fb,   // [P+1][2*CIN] hi|lo
                const int* __restrict__ nbr,
                const uint8_t* __restrict__ blob,
                float* __restrict__ out,
                int rows, int P) {
    constexpr int NK = CIN / 16;              // ksteps per pass
    constexpr int NT = COUT / 8;              // n tiles
    constexpr int PITCH2 = (2 * CIN + 8) * 2; // bytes per A row (+16B pad)
    constexpr int HCH = CIN / 8;              // uint4 per half-row
    constexpr int BSTR = 2 * NK * NT * 32;    // uint2 per tap blob

    __shared__ __align__(16) uint8_t As[8][16 * PITCH2];

    int tid = threadIdx.x;
    int w = tid >> 5, lane = tid & 31;
    int r = lane & 15, h = lane >> 4;
    int row0 = blockIdx.x * 128;

    int myrow = row0 + w * 16 + r;
    bool gv = (myrow < rows);

    uint32_t abase = smem_u32(As[w]);
    uint32_t my_sts = abase + (uint32_t)(r * PITCH2 + h * (2 * CIN));
    uint32_t ldm_base = abase + (uint32_t)(r * PITCH2 + h * 16);

    const uint2* Bblob = reinterpret_cast<const uint2*>(blob);

    float acc[NT][4];
#pragma unroll
    for (int nt = 0; nt < NT; nt++)
#pragma unroll
        for (int j = 0; j < 4; j++) acc[nt][j] = 0.f;

    int idx_nxt = gv ? __ldg(&nbr[0 * (size_t)rows + myrow]) : P;

#pragma unroll 1
    for (int k = 0; k < K; k++) {
        int idx = idx_nxt;
        if (k + 1 < K)
            idx_nxt = gv ? __ldg(&nbr[(size_t)(k + 1) * rows + myrow]) : P;

        unsigned pres = __ballot_sync(0xFFFFFFFFu, idx != P) & 0xFFFFu;
        if (pres == 0) continue;                 // warp-tap skip (exact)

        // gather: lane (r, h) loads half h of row r (sentinel -> zero pad row)
        const uint4* src = reinterpret_cast<const uint4*>(
            fb + (size_t)idx * 2 * CIN) + h * HCH;
#pragma unroll
        for (int c = 0; c < HCH; c++) sts128(my_sts + c * 16u, __ldg(src + c));
        __syncwarp();

        const uint2* Bk = Bblob + (size_t)k * BSTR;
#pragma unroll
        for (int g = 0; g < NK; g++) {
            uint32_t ah[4], al[4];
            ldm_x4(ah, ldm_base + (uint32_t)(g * 32));
            ldm_x4(al, ldm_base + (uint32_t)(CIN * 2 + g * 32));
#pragma unroll
            for (int nt = 0; nt < NT; nt++) {
                uint2 bh = __ldg(&Bk[((g)      * NT + nt) * 32 + lane]);
                uint2 bl = __ldg(&Bk[((NK + g) * NT + nt) * 32 + lane]);
                mma16816(acc[nt], ah, bh);
                mma16816(acc[nt], ah, bl);
                mma16816(acc[nt], al, bh);
            }
        }
        __syncwarp();
    }

    // epilogue: m16n8 fragment -> rows gid and gid+8
    int gid = lane >> 2, t = lane & 3;
    int r0 = row0 + w * 16 + gid;
#pragma unroll
    for (int nt = 0; nt < NT; nt++) {
        int cbase = nt * 8 + 2 * t;
        if (r0 < rows)
            *reinterpret_cast<float2*>(&out[(size_t)r0 * COUT + cbase]) =
                make_float2(acc[nt][0], acc[nt][1]);
        if (r0 + 8 < rows)
            *reinterpret_cast<float2*>(&out[(size_t)(r0 + 8) * COUT + cbase]) =
                make_float2(acc[nt][2], acc[nt][3]);
    }
}

// ---------------------------------------------------------------------------
// Stride-2 transpose conv (deconv), ALL 8 taps in one launch (64KB dyn smem):
// out[n] = g[up_cidx[n]] @ W[up_k[n]]
// ---------------------------------------------------------------------------
__global__ __launch_bounds__(256) void deconv_all(const float* __restrict__ g,
                                                  const int* __restrict__ up_cidx,
                                                  const int* __restrict__ up_k,
                                                  const float* __restrict__ Wup,
                                                  float* __restrict__ out,
                                                  int nrows) {
    extern __shared__ float Ws8[];   // [8][64][32] = 64 KB
    int tid = threadIdx.x;
    const float4* src = reinterpret_cast<const float4*>(Wup);
    for (int v = tid; v < 8 * 64 * 32 / 4; v += 256)
        reinterpret_cast<float4*>(Ws8)[v] = src[v];
    __syncthreads();

    int warp = tid >> 5, lane = tid & 31;
    int base = blockIdx.x * 64 + warp * 8;
#pragma unroll
    for (int i = 0; i < 8; i++) {
        int row = base + i;
        if (row >= nrows) break;
        int k = up_k[row];
        const float* Wk = Ws8 + k * 2048;
        int cid = up_cidx[row];
        const float* grow = g + (size_t)cid * 64;
        float xa = grow[lane], xb = grow[lane + 32];
        float acc = 0.f;
#pragma unroll
        for (int cin = 0; cin < 64; cin++) {
            float xv = __shfl_sync(0xFFFFFFFFu, (cin < 32) ? xa : xb, cin & 31);
            acc = fmaf(xv, Wk[cin * 32 + lane], acc);
        }
        out[(size_t)row * 32 + lane] = acc;
    }
}

// ---------------------------------------------------------------------------
// Host launcher
// ---------------------------------------------------------------------------
static void* sym_addr(const void* s) {
    void* p = nullptr;
    cudaGetSymbolAddress(&p, s);
    return p;
}

extern "C" void kernel_launch(void* const* d_in, const int* in_sizes, int n_in,
                              void* d_out, int out_size) {
    const float* feat    = (const float*)d_in[0];
    const float* w_sub1  = (const float*)d_in[1];
    const float* w_down  = (const float*)d_in[2];
    const float* w_sub2  = (const float*)d_in[3];
    const float* w_up    = (const float*)d_in[4];
    const float* w_sub3  = (const float*)d_in[5];
    const float* g1 = (const float*)d_in[6];  const float* b1 = (const float*)d_in[7];
    const float* g2 = (const float*)d_in[8];  const float* b2 = (const float*)d_in[9];
    const float* g3 = (const float*)d_in[10]; const float* b3 = (const float*)d_in[11];
    const float* g4 = (const float*)d_in[12]; const float* b4 = (const float*)d_in[13];
    const float* g5 = (const float*)d_in[14]; const float* b5 = (const float*)d_in[15];
    const int* nbr_fine   = (const int*)d_in[16];
    const int* nbr_coarse = (const int*)d_in[17];
    const int* down_idx   = (const int*)d_in[18];
    const int* up_cidx    = (const int*)d_in[19];
    const int* up_k       = (const int*)d_in[20];

    int N = in_sizes[0] / 32;
    int M = in_sizes[18] / 8;

    __nv_bfloat16* t0b = (__nv_bfloat16*)sym_addr(g_t0b);
    __nv_bfloat16* t1b = (__nv_bfloat16*)sym_addr(g_t1b);
    __nv_bfloat16* t2b = (__nv_bfloat16*)sym_addr(g_t2b);
    __nv_bfloat16* t4b = (__nv_bfloat16*)sym_addr(g_t4b);
    float*  x1   = (float*)sym_addr(g_x1);
    float*  xc0  = (float*)sym_addr(g_xc0);
    float*  xc1  = (float*)sym_addr(g_xc1);
    float*  t3   = (float*)sym_addr(g_t3);
    float*  xf   = (float*)sym_addr(g_xf);
    float*  part = (float*)sym_addr(g_partf);
    int*    ctr  = (int*)sym_addr(&g_ctr);
    float*  sc   = (float*)sym_addr(g_scale);
    float*  sh   = (float*)sym_addr(g_shift);
    uint8_t* wb1 = (uint8_t*)sym_addr(g_wb1);
    uint8_t* wbD = (uint8_t*)sym_addr(g_wbD);
    uint8_t* wb2 = (uint8_t*)sym_addr(g_wb2);
    uint8_t* wb3 = (uint8_t*)sym_addr(g_wb3);
    float*  outp = (float*)d_out;

    auto cdiv = [](int a, int b) { return (a + b - 1) / b; };

    cudaFuncSetAttribute((const void*)deconv_all,
                         cudaFuncAttributeMaxDynamicSharedMemorySize, 65536);

    // W fragment prep (deterministic, idempotent)
    wprep<32, 32, 27><<<cdiv(27 * 32 * 32, 256), 256>>>(w_sub1, wb1);
    wprep<32, 64, 8><<<cdiv(8 * 32 * 64, 256), 256>>>(w_down, wbD);
    wprep<64, 64, 27><<<cdiv(27 * 64 * 64, 256), 256>>>(w_sub2, wb2);
    wprep<64, 32, 27><<<cdiv(27 * 64 * 32, 256), 256>>>(w_sub3, wb3);

    // stage 1: BN1(feat) -> t0b ; sub1 -> x1
    bn_stats_fused<32><<<NBLK_STATS, 256>>>(feat, N, g1, b1,
                                            sc + 0 * 64, sh + 0 * 64, part, ctr);
    bn_apply_split<32><<<cdiv(N * 8, 256), 256>>>(feat, t0b, sc + 0 * 64, sh + 0 * 64, N);
    conv_mma16<32, 32, 27, 3><<<cdiv(N, 128), 256>>>(t0b, nbr_fine, wb1, x1, N, N);

    // stage 2: BN2(x1) -> t1b ; down -> xc0
    bn_stats_fused<32><<<NBLK_STATS, 256>>>(x1, N, g2, b2,
                                            sc + 1 * 64, sh + 1 * 64, part, ctr);
    bn_apply_split<32><<<cdiv(N * 8, 256), 256>>>(x1, t1b, sc + 1 * 64, sh + 1 * 64, N);
    conv_mma16<32, 64, 8, 2><<<cdiv(M, 128), 256>>>(t1b, down_idx, wbD, xc0, M, N);

    // stage 3: BN3(xc0) -> t2b ; sub2 -> xc1
    bn_stats_fused<64><<<NBLK_STATS, 256>>>(xc0, M, g3, b3,
                                            sc + 2 * 64, sh + 2 * 64, part, ctr);
    bn_apply_split<64><<<cdiv(M * 16, 256), 256>>>(xc0, t2b, sc + 2 * 64, sh + 2 * 64, M);
    conv_mma16<64, 64, 27, 2><<<cdiv(M, 128), 256>>>(t2b, nbr_coarse, wb2, xc1, M, M);

    // stage 4: BN4(xc1) -> t3 (fp32) ; deconv -> xf (single launch)
    bn_stats_fused<64><<<NBLK_STATS, 256>>>(xc1, M, g4, b4,
                                            sc + 3 * 64, sh + 3 * 64, part, ctr);
    bn_apply<64><<<cdiv(M * 16, 256), 256>>>(xc1, t3, sc + 3 * 64, sh + 3 * 64, M);
    deconv_all<<<cdiv(N, 64), 256, 65536>>>(t3, up_cidx, up_k, w_up, xf, N);

    // stage 5: BN5(concat(x1, xf)) -> t4b ; sub3 -> out
    bn_stats_fused<32><<<NBLK_STATS, 256>>>(x1, N, g5, b5,
                                            sc + 4 * 64, sh + 4 * 64, part, ctr);
    bn_stats_fused<32><<<NBLK_STATS, 256>>>(xf, N, g5 + 32, b5 + 32,
                                            sc + 4 * 64 + 32, sh + 4 * 64 + 32,
                                            part, ctr);
    bn_apply_cat_split<<<cdiv(N * 16, 256), 256>>>(x1, xf, t4b,
                                                   sc + 4 * 64, sh + 4 * 64, N);
    conv_mma16<64, 32, 27, 3><<<cdiv(N, 128), 256>>>(t4b, nbr_fine, wb3, outp, N, N);
}